// round 2
// baseline (speedup 1.0000x reference)
#include <cuda_runtime.h>
#include <cstdint>

// BlockDiagonal: out[64,8192] = x[64,8192] @ (blocks * block_diag_mask)
// Only the 32 diagonal 256x256 blocks of `blocks` contribute.
//
// Decomposition: 32 diag blocks x 4 column chunks (64 cols) = 128 CTAs.
// Each CTA: out[0:64, col0:col0+64] = x[0:64, k0:k0+256] @ B[k0:k0+256, col0:col0+64]
//
// fp32 math via packed fma.rn.f32x2 (SASS FFMA2, 2x FLOP/issue).
// x slice stored transposed + duplicated in smem: x_d[k][2m] = (x[m][k], x[m][k])
// so each LDS.128 yields two ready f32x2 multiplicands (no pack instructions).
// B tile double-buffered via cp.async in K-chunks of 64.
//
// R1 fix: compute loop must index xd with the GLOBAL block-local k (c*KC+kk),
// not the chunk-local kk.

#define KBLK     256   // diagonal block size (K per CTA)
#define CHUNK_N  64    // output columns per CTA
#define KC       64    // K chunk for cp.async pipeline
#define NROW     8192
#define BATCH    64
#define XD_STRIDE 132  // 128 duplicated floats + 4 pad (528B, 16B aligned)

#define SMEM_FLOATS (KBLK * XD_STRIDE + 2 * KC * CHUNK_N)  // 33792 + 8192 = 41984 floats
#define SMEM_BYTES  (SMEM_FLOATS * 4)                      // 167936 bytes

__device__ __forceinline__ void ffma2(unsigned long long& d,
                                      unsigned long long a,
                                      unsigned long long b) {
    asm volatile("fma.rn.f32x2 %0, %1, %2, %0;" : "+l"(d) : "l"(a), "l"(b));
}

__device__ __forceinline__ void cp_async16(uint32_t s, const void* g) {
    asm volatile("cp.async.cg.shared.global [%0], [%1], 16;" :: "r"(s), "l"(g));
}

__global__ void __launch_bounds__(256, 1)
block_diag_kernel(const float* __restrict__ x,
                  const float* __restrict__ blocks,
                  float* __restrict__ out) {
    extern __shared__ float smem[];
    float* xd = smem;                       // [KBLK][XD_STRIDE] duplicated-transposed x
    float* bs = smem + KBLK * XD_STRIDE;    // [2][KC][CHUNK_N] B ring

    const int tid   = threadIdx.x;
    const int bx    = blockIdx.x;
    const int dblk  = bx >> 2;              // diagonal block index 0..31
    const int chunk = bx & 3;               // column chunk 0..3
    const int k0    = dblk * KBLK;          // K / row base in blocks
    const int col0  = k0 + chunk * CHUNK_N; // output / B column base

    const uint32_t bs_u32 = (uint32_t)__cvta_generic_to_shared(bs);

    // ---- issue one B chunk (64 rows x 64 cols) via cp.async, 4x16B per thread ----
    auto issueB = [&](int c, int buf) {
        #pragma unroll
        for (int q = 0; q < 4; ++q) {
            int idx = q * 256 + tid;
            int kr  = idx >> 4;       // 0..63 chunk-local row
            int n4  = idx & 15;       // 0..15 float4 within 64 cols
            const float* g = blocks + (size_t)(k0 + c * KC + kr) * NROW + col0 + n4 * 4;
            cp_async16(bs_u32 + (uint32_t)(((buf * KC + kr) * CHUNK_N + n4 * 4) * 4), g);
        }
        asm volatile("cp.async.commit_group;" ::: "memory");
    };

    // Prologue: start B chunks 0 and 1
    issueB(0, 0);
    issueB(1, 1);

    // ---- load the full x slice [64][256], transpose + duplicate into smem ----
    // 64*64 float4 tiles / 256 threads = 16 per thread
    #pragma unroll 4
    for (int p = 0; p < 16; ++p) {
        int idx = p * 256 + tid;
        int m   = idx >> 6;           // 0..63
        int k4  = idx & 63;           // 0..63 (float4 index along K)
        float4 v = *(const float4*)(x + (size_t)m * NROW + k0 + k4 * 4);
        int kb = k4 * 4;
        const float* vv = &v.x;
        #pragma unroll
        for (int j = 0; j < 4; ++j) {
            float t = vv[j];
            *(float2*)(xd + (kb + j) * XD_STRIDE + 2 * m) = make_float2(t, t);
        }
    }

    asm volatile("cp.async.wait_group 1;" ::: "memory");  // chunk 0 landed
    __syncthreads();                                       // + x transpose visible

    // ---- thread tile: 4 m-rows x 4 n-cols ----
    const int tn = tid & 15;          // 16 threads along n, 4 cols each
    const int tm = tid >> 4;          // 16 threads along m, 4 rows each
    const int n0 = tn * 4;
    const int m0 = tm * 4;

    unsigned long long acc[4][2];     // [mi][col-pair], f32x2 accumulators
    #pragma unroll
    for (int i = 0; i < 4; ++i) { acc[i][0] = 0ull; acc[i][1] = 0ull; }

    #pragma unroll 1
    for (int c = 0; c < 4; ++c) {
        const float* bsbuf = bs + (c & 1) * KC * CHUNK_N;
        const float* xbase = xd + (c * KC) * XD_STRIDE + 2 * m0;  // R1 FIX: global k offset
        #pragma unroll 16
        for (int kk = 0; kk < KC; ++kk) {
            const float* xr = xbase + kk * XD_STRIDE;
            ulonglong2 xA = *(const ulonglong2*)(xr);       // xx[m0], xx[m0+1]
            ulonglong2 xB = *(const ulonglong2*)(xr + 4);   // xx[m0+2], xx[m0+3]
            ulonglong2 bV = *(const ulonglong2*)(bsbuf + kk * CHUNK_N + n0); // b01, b23
            ffma2(acc[0][0], xA.x, bV.x);  ffma2(acc[0][1], xA.x, bV.y);
            ffma2(acc[1][0], xA.y, bV.x);  ffma2(acc[1][1], xA.y, bV.y);
            ffma2(acc[2][0], xB.x, bV.x);  ffma2(acc[2][1], xB.x, bV.y);
            ffma2(acc[3][0], xB.y, bV.x);  ffma2(acc[3][1], xB.y, bV.y);
        }
        if (c < 3) {
            __syncthreads();                 // done reading buffer (c&1)
            if (c < 2) {
                issueB(c + 2, c & 1);
                asm volatile("cp.async.wait_group 1;" ::: "memory");  // chunk c+1 landed
            } else {
                asm volatile("cp.async.wait_group 0;" ::: "memory");  // chunk 3 landed
            }
            __syncthreads();
        }
    }

    // ---- epilogue: unpack and store 4x4 tile, STG.128 per row ----
    #pragma unroll
    for (int mi = 0; mi < 4; ++mi) {
        float2 p0 = *(float2*)&acc[mi][0];
        float2 p1 = *(float2*)&acc[mi][1];
        float4 o = make_float4(p0.x, p0.y, p1.x, p1.y);
        *(float4*)(out + (size_t)(m0 + mi) * NROW + col0 + n0) = o;
    }
}

extern "C" void kernel_launch(void* const* d_in, const int* in_sizes, int n_in,
                              void* d_out, int out_size) {
    const float* x      = (const float*)d_in[0];
    const float* blocks = (const float*)d_in[1];
    // d_in[2] is the mask; it is block-diagonal by construction, structure is hardcoded.
    float* out = (float*)d_out;

    cudaFuncSetAttribute(block_diag_kernel,
                         cudaFuncAttributeMaxDynamicSharedMemorySize, SMEM_BYTES);
    block_diag_kernel<<<128, 256, SMEM_BYTES>>>(x, blocks, out);
}

// round 3
// speedup vs baseline: 1.1404x; 1.1404x over previous
#include <cuda_runtime.h>
#include <cstdint>

// BlockDiagonal: out[64,8192] = x[64,8192] @ (blocks * block_diag_mask)
// 32 diagonal 256x256 blocks; CTA = one block x one 64-col chunk. Grid 128.
//
// R3 redesign:
//  - x kept ROW-MAJOR in smem (no transpose, no duplication, conflict-free):
//    (v,v) f32x2 operands built with mov.b64 {v,v} in-loop.
//  - 512 threads (16 warps) per CTA, thread tile 2m x 4n -> FMA-pipe bound.
//  - B double-buffered via cp.async in 64-k chunks (unchanged scheme).

#define KBLK     256
#define CHUNK_N  64
#define KC       64
#define NROW     8192
#define XS       260            // x row stride in floats (256 + 4 pad)

#define SMEM_FLOATS (64 * XS + 2 * KC * CHUNK_N)   // 16640 + 8192 = 24832
#define SMEM_BYTES  (SMEM_FLOATS * 4)              // 99328 bytes

__device__ __forceinline__ void ffma2(unsigned long long& d,
                                      unsigned long long a,
                                      unsigned long long b) {
    asm volatile("fma.rn.f32x2 %0, %1, %2, %0;" : "+l"(d) : "l"(a), "l"(b));
}

__device__ __forceinline__ unsigned long long dup2(float v) {
    unsigned long long r;
    asm("mov.b64 %0, {%1, %1};" : "=l"(r) : "f"(v));
    return r;
}

__device__ __forceinline__ void cp_async16(uint32_t s, const void* g) {
    asm volatile("cp.async.cg.shared.global [%0], [%1], 16;" :: "r"(s), "l"(g));
}

__global__ void __launch_bounds__(512, 1)
block_diag_kernel(const float* __restrict__ x,
                  const float* __restrict__ blocks,
                  float* __restrict__ out) {
    extern __shared__ float smem[];
    float* xs = smem;                 // [64][XS] row-major x slice
    float* bs = smem + 64 * XS;       // [2][KC][CHUNK_N] B ring

    const int tid   = threadIdx.x;
    const int bx    = blockIdx.x;
    const int dblk  = bx >> 2;
    const int chunk = bx & 3;
    const int k0    = dblk * KBLK;
    const int col0  = k0 + chunk * CHUNK_N;

    const uint32_t bs_u32 = (uint32_t)__cvta_generic_to_shared(bs);

    // ---- one B chunk (64 rows x 64 cols) via cp.async: 2 x 16B per thread ----
    auto issueB = [&](int c, int buf) {
        #pragma unroll
        for (int q = 0; q < 2; ++q) {
            int idx = q * 512 + tid;
            int kr  = idx >> 4;       // 0..63
            int n4  = idx & 15;       // 0..15
            const float* g = blocks + (size_t)(k0 + c * KC + kr) * NROW + col0 + n4 * 4;
            cp_async16(bs_u32 + (uint32_t)(((buf * KC + kr) * CHUNK_N + n4 * 4) * 4), g);
        }
        asm volatile("cp.async.commit_group;" ::: "memory");
    };

    issueB(0, 0);
    issueB(1, 1);

    // ---- load x slice [64][256] row-major: coalesced LDG.128 + conflict-free STS.128 ----
    // 4096 float4 / 512 threads = 8 per thread
    #pragma unroll
    for (int p = 0; p < 8; ++p) {
        int idx = p * 512 + tid;
        int m   = idx >> 6;           // 0..63
        int k4  = idx & 63;           // 0..63
        float4 v = *(const float4*)(x + (size_t)m * NROW + k0 + k4 * 4);
        *(float4*)(xs + m * XS + k4 * 4) = v;
    }

    asm volatile("cp.async.wait_group 1;" ::: "memory");
    __syncthreads();

    // ---- thread tile: 2 m-rows x 4 n-cols; 16 tn x 32 tm ----
    const int tn = tid & 15;
    const int tm = tid >> 4;          // 0..31
    const int n0 = tn * 4;
    const int m0 = tm * 2;

    unsigned long long acc[2][2];     // [mi][n-pair]
    acc[0][0] = acc[0][1] = acc[1][0] = acc[1][1] = 0ull;

    const float* xr0 = xs + m0 * XS;
    const float* xr1 = xs + (m0 + 1) * XS;

    #pragma unroll 1
    for (int c = 0; c < 4; ++c) {
        const float* bsbuf = bs + (c & 1) * KC * CHUNK_N + n0;
        const int kbase = c * KC;
        #pragma unroll 4
        for (int kk4 = 0; kk4 < KC; kk4 += 4) {
            // x for 4 consecutive k, 2 m rows (16-lane smem broadcast)
            float4 xa = *(const float4*)(xr0 + kbase + kk4);
            float4 xb = *(const float4*)(xr1 + kbase + kk4);
            const float* xaf = &xa.x;
            const float* xbf = &xb.x;
            #pragma unroll
            for (int j = 0; j < 4; ++j) {
                ulonglong2 bV = *(const ulonglong2*)(bsbuf + (kk4 + j) * CHUNK_N);
                unsigned long long a0 = dup2(xaf[j]);
                unsigned long long a1 = dup2(xbf[j]);
                ffma2(acc[0][0], a0, bV.x);
                ffma2(acc[0][1], a0, bV.y);
                ffma2(acc[1][0], a1, bV.x);
                ffma2(acc[1][1], a1, bV.y);
            }
        }
        if (c < 3) {
            __syncthreads();
            if (c < 2) {
                issueB(c + 2, c & 1);
                asm volatile("cp.async.wait_group 1;" ::: "memory");
            } else {
                asm volatile("cp.async.wait_group 0;" ::: "memory");
            }
            __syncthreads();
        }
    }

    // ---- epilogue: 2 rows x STG.128 ----
    #pragma unroll
    for (int mi = 0; mi < 2; ++mi) {
        float2 p0 = *(float2*)&acc[mi][0];
        float2 p1 = *(float2*)&acc[mi][1];
        float4 o = make_float4(p0.x, p0.y, p1.x, p1.y);
        *(float4*)(out + (size_t)(m0 + mi) * NROW + col0 + n0) = o;
    }
}

extern "C" void kernel_launch(void* const* d_in, const int* in_sizes, int n_in,
                              void* d_out, int out_size) {
    const float* x      = (const float*)d_in[0];
    const float* blocks = (const float*)d_in[1];
    float* out = (float*)d_out;

    cudaFuncSetAttribute(block_diag_kernel,
                         cudaFuncAttributeMaxDynamicSharedMemorySize, SMEM_BYTES);
    block_diag_kernel<<<128, 512, SMEM_BYTES>>>(x, blocks, out);
}

// round 5
// speedup vs baseline: 1.9770x; 1.7336x over previous
#include <cuda_runtime.h>
#include <cuda_bf16.h>
#include <cstdint>

// out[64,8192] = x[64,8192] @ blockdiag(blocks), 32 diagonal 256x256 blocks.
// Grid 128 = 32 blocks x 4 col-chunks of 64. Per CTA:
//   out[0:64, col0:col0+64] = x[0:64, k0:k0+256] @ B[k0:k0+256, col0:col0+64]
//
// sm_103 (no 'a' features available in this build): warp-level bf16 HMMA via
// mma.sync.m16n8k16 + ldmatrix. fp32 accuracy via 3-term bf16 split:
//   x = xh + xl, B = Bh + Bl;  out ~= xh@Bh + xh@Bl + xl@Bh   (xl@Bl ~ 2^-18, dropped)
//
// 16 warps = 4x4 grid of 16x16 output tiles, K=256 = 16 k-steps.
// A smem: [64 rows][256 bf16] (512B/row), xor-swizzled at 16B granules.
// B smem: [256 rows][64 bf16] (128B/row), natural [k][n], read via ldmatrix.trans.

#define NROW 8192

#define OFF_AH 0         // 32KB
#define OFF_AL 32768     // 32KB
#define OFF_BH 65536     // 32KB
#define OFF_BL 98304     // 32KB
#define SMEM_BYTES 131072

__device__ __forceinline__ uint32_t smem_u32(const void* p) {
    uint32_t a;
    asm("{ .reg .u64 t; cvta.to.shared.u64 t, %1; cvt.u32.u64 %0, t; }" : "=r"(a) : "l"(p));
    return a;
}

__device__ __forceinline__ void ldsm_x4(uint32_t* r, uint32_t addr) {
    asm volatile("ldmatrix.sync.aligned.m8n8.x4.shared.b16 {%0,%1,%2,%3}, [%4];"
                 : "=r"(r[0]), "=r"(r[1]), "=r"(r[2]), "=r"(r[3]) : "r"(addr));
}
__device__ __forceinline__ void ldsm_x4_t(uint32_t* r, uint32_t addr) {
    asm volatile("ldmatrix.sync.aligned.m8n8.x4.trans.shared.b16 {%0,%1,%2,%3}, [%4];"
                 : "=r"(r[0]), "=r"(r[1]), "=r"(r[2]), "=r"(r[3]) : "r"(addr));
}
__device__ __forceinline__ void mma_bf16(float* d, const uint32_t* a, uint32_t b0, uint32_t b1) {
    asm volatile(
        "mma.sync.aligned.m16n8k16.row.col.f32.bf16.bf16.f32 "
        "{%0,%1,%2,%3}, {%4,%5,%6,%7}, {%8,%9}, {%0,%1,%2,%3};"
        : "+f"(d[0]), "+f"(d[1]), "+f"(d[2]), "+f"(d[3])
        : "r"(a[0]), "r"(a[1]), "r"(a[2]), "r"(a[3]), "r"(b0), "r"(b1));
}

// split float pair -> (h bf16x2, l bf16x2)
__device__ __forceinline__ void split2(float a, float b, uint32_t& h, uint32_t& l) {
    __nv_bfloat162 hh = __floats2bfloat162_rn(a, b);
    float ra = a - __bfloat162float(hh.x);
    float rb = b - __bfloat162float(hh.y);
    __nv_bfloat162 ll = __floats2bfloat162_rn(ra, rb);
    h = *(uint32_t*)&hh;
    l = *(uint32_t*)&ll;
}

__global__ void __launch_bounds__(512, 1)
block_diag_hmma(const float* __restrict__ x,
                const float* __restrict__ blocks,
                float* __restrict__ out) {
    extern __shared__ char smem[];
    const uint32_t sbase = smem_u32(smem);

    const int tid   = threadIdx.x;
    const int wid   = tid >> 5;
    const int lid   = tid & 31;
    const int bx    = blockIdx.x;
    const int dblk  = bx >> 2;
    const int chunk = bx & 3;
    const int k0    = dblk * 256;
    const int col0  = k0 + chunk * 64;

    // ---- stage A: x[64][256] fp32 -> Ah/Al bf16, swizzled ----
    // 4096 float4 / 512 threads = 8 per thread. Row = 512B = 32 granules of 16B.
    #pragma unroll
    for (int p = 0; p < 8; ++p) {
        int idx = p * 512 + tid;
        int m   = idx >> 6;          // 0..63
        int k4  = idx & 63;          // float4 index along K
        float4 v = *(const float4*)(x + (size_t)m * NROW + k0 + k4 * 4);
        uint32_t h01, l01, h23, l23;
        split2(v.x, v.y, h01, l01);
        split2(v.z, v.w, h23, l23);
        int g = k4 >> 1, hh = k4 & 1;
        uint32_t off = (uint32_t)(m * 512 + ((g ^ (m & 7)) * 16 + hh * 8));
        *(uint2*)(smem + OFF_AH + off) = make_uint2(h01, h23);
        *(uint2*)(smem + OFF_AL + off) = make_uint2(l01, l23);
    }

    // ---- stage B: blocks[256][64] fp32 -> Bh/Bl bf16, swizzled ----
    // 4096 float4 / 512 threads = 8 per thread. Row = 128B = 8 granules.
    #pragma unroll
    for (int p = 0; p < 8; ++p) {
        int idx = p * 512 + tid;
        int k   = idx >> 4;          // 0..255
        int n4  = idx & 15;
        float4 v = *(const float4*)(blocks + (size_t)(k0 + k) * NROW + col0 + n4 * 4);
        uint32_t h01, l01, h23, l23;
        split2(v.x, v.y, h01, l01);
        split2(v.z, v.w, h23, l23);
        int g = n4 >> 1, hh = n4 & 1;
        uint32_t off = (uint32_t)(k * 128 + ((g ^ (k & 7)) * 16 + hh * 8));
        *(uint2*)(smem + OFF_BH + off) = make_uint2(h01, h23);
        *(uint2*)(smem + OFF_BL + off) = make_uint2(l01, l23);
    }

    __syncthreads();

    // ---- compute: warp (wm, wn) owns out tile [wm*16 .. +16) x [wn*16 .. +16) ----
    const int wm = wid & 3;
    const int wn = wid >> 2;
    const int m_base = wm * 16;
    const int n_base = wn * 16;

    // A ldmatrix lane address components (row-major A, 16x16 tile, .x4):
    // lane l -> row = m_base + (l & 15), col-half ch = l >> 4
    const int a_row = m_base + (lid & 15);
    const int a_ch  = lid >> 4;
    const int a_rx  = a_row & 7;
    const uint32_t a_rowbase = (uint32_t)(a_row * 512);

    // B ldmatrix lane address (row-major [k][n], .x4.trans):
    // lane l -> k-row = ks*16 + (l & 15), n-col-half = wn*2 + (l >> 4)
    // (k-row & 7) == (l & 7) since ks*16 % 8 == 0
    const int b_g   = (wn * 2 + (lid >> 4)) ^ (lid & 7);
    const uint32_t b_base = (uint32_t)((lid & 15) * 128 + b_g * 16);

    float acc[2][4] = {};
    uint32_t ah[4], al[4], bh[4], bl[4];

    #pragma unroll
    for (int ks = 0; ks < 16; ++ks) {
        uint32_t a_off = a_rowbase + (uint32_t)((((ks * 2 + a_ch) ^ a_rx)) * 16);
        uint32_t b_off = b_base + (uint32_t)(ks * 2048);
        ldsm_x4(ah, sbase + OFF_AH + a_off);
        ldsm_x4(al, sbase + OFF_AL + a_off);
        ldsm_x4_t(bh, sbase + OFF_BH + b_off);
        ldsm_x4_t(bl, sbase + OFF_BL + b_off);

        mma_bf16(acc[0], ah, bh[0], bh[1]);
        mma_bf16(acc[1], ah, bh[2], bh[3]);
        mma_bf16(acc[0], ah, bl[0], bl[1]);
        mma_bf16(acc[1], ah, bl[2], bl[3]);
        mma_bf16(acc[0], al, bh[0], bh[1]);
        mma_bf16(acc[1], al, bh[2], bh[3]);
    }

    // ---- epilogue: mma D fragment -> gmem ----
    // thread t: rows (t>>2) and (t>>2)+8; cols (t&3)*2 + {0,1} per n-half
    const int grp = lid >> 2;
    const int tc  = lid & 3;
    const int row0 = m_base + grp;
    const int row1 = row0 + 8;
    #pragma unroll
    for (int nh = 0; nh < 2; ++nh) {
        int col = col0 + n_base + nh * 8 + tc * 2;
        *(float2*)(out + (size_t)row0 * NROW + col) = make_float2(acc[nh][0], acc[nh][1]);
        *(float2*)(out + (size_t)row1 * NROW + col) = make_float2(acc[nh][2], acc[nh][3]);
    }
}

extern "C" void kernel_launch(void* const* d_in, const int* in_sizes, int n_in,
                              void* d_out, int out_size) {
    const float* x      = (const float*)d_in[0];
    const float* blocks = (const float*)d_in[1];
    float* out = (float*)d_out;

    cudaFuncSetAttribute(block_diag_hmma,
                         cudaFuncAttributeMaxDynamicSharedMemorySize, SMEM_BYTES);
    block_diag_hmma<<<128, 512, SMEM_BYTES>>>(x, blocks, out);
}

// round 6
// speedup vs baseline: 2.2177x; 1.1218x over previous
#include <cuda_runtime.h>
#include <cuda_bf16.h>
#include <cstdint>

// out[64,8192] = x[64,8192] @ blockdiag(blocks), 32 diagonal 256x256 blocks.
// Grid 128 = 32 blocks x 4 col-chunks of 64. Per CTA:
//   out[0:64, col0:col0+64] = x[0:64, k0:k0+256] @ B[k0:k0+256, col0:col0+64]
//
// bf16 HMMA (mma.sync.m16n8k16) with 3-term split: xh@Bh + xh@Bl + xl@Bh.
// R6: K pipelined in 4 chunks of 64, double-buffered smem, LDG prefetch
// distance 2 so DRAM latency and split/convert ALU overlap HMMA.

#define NROW 8192

#define CHUNK_B  8192            // one bf16 buffer: 64 rows x 128B
#define OFF_AH   0               // [2] bufs
#define OFF_AL   16384
#define OFF_BH   32768
#define OFF_BL   49152
#define SMEM_BYTES 65536

__device__ __forceinline__ uint32_t smem_u32(const void* p) {
    uint32_t a;
    asm("{ .reg .u64 t; cvta.to.shared.u64 t, %1; cvt.u32.u64 %0, t; }" : "=r"(a) : "l"(p));
    return a;
}
__device__ __forceinline__ void ldsm_x4(uint32_t* r, uint32_t addr) {
    asm volatile("ldmatrix.sync.aligned.m8n8.x4.shared.b16 {%0,%1,%2,%3}, [%4];"
                 : "=r"(r[0]), "=r"(r[1]), "=r"(r[2]), "=r"(r[3]) : "r"(addr));
}
__device__ __forceinline__ void ldsm_x4_t(uint32_t* r, uint32_t addr) {
    asm volatile("ldmatrix.sync.aligned.m8n8.x4.trans.shared.b16 {%0,%1,%2,%3}, [%4];"
                 : "=r"(r[0]), "=r"(r[1]), "=r"(r[2]), "=r"(r[3]) : "r"(addr));
}
__device__ __forceinline__ void mma_bf16(float* d, const uint32_t* a, uint32_t b0, uint32_t b1) {
    asm volatile(
        "mma.sync.aligned.m16n8k16.row.col.f32.bf16.bf16.f32 "
        "{%0,%1,%2,%3}, {%4,%5,%6,%7}, {%8,%9}, {%0,%1,%2,%3};"
        : "+f"(d[0]), "+f"(d[1]), "+f"(d[2]), "+f"(d[3])
        : "r"(a[0]), "r"(a[1]), "r"(a[2]), "r"(a[3]), "r"(b0), "r"(b1));
}
__device__ __forceinline__ void split2(float a, float b, uint32_t& h, uint32_t& l) {
    __nv_bfloat162 hh = __floats2bfloat162_rn(a, b);
    float ra = a - __bfloat162float(hh.x);
    float rb = b - __bfloat162float(hh.y);
    __nv_bfloat162 ll = __floats2bfloat162_rn(ra, rb);
    h = *(uint32_t*)&hh;
    l = *(uint32_t*)&ll;
}

__global__ void __launch_bounds__(512, 1)
block_diag_hmma(const float* __restrict__ x,
                const float* __restrict__ blocks,
                float* __restrict__ out) {
    extern __shared__ char smem[];
    const uint32_t sbase = smem_u32(smem);

    const int tid   = threadIdx.x;
    const int wid   = tid >> 5;
    const int lid   = tid & 31;
    const int bx    = blockIdx.x;
    const int dblk  = bx >> 2;
    const int chunk = bx & 3;
    const int k0    = dblk * 256;
    const int col0  = k0 + chunk * 64;

    // per-thread staging coordinates (same for both idx passes p=0,1)
    const int sm0 = tid >> 4;            // A row / B k-row for p=0 (0..31)
    const int sq  = tid & 15;            // float4 index within row
    // p=1 adds 32 to the row.

    // ---- LDG one chunk into regs: 2 A float4 + 2 B float4 ----
    auto ldgChunk = [&](int c, float4* ra, float4* rb) {
        const int kg = k0 + c * 64;
        #pragma unroll
        for (int p = 0; p < 2; ++p) {
            int m = sm0 + p * 32;
            ra[p] = *(const float4*)(x + (size_t)m * NROW + kg + sq * 4);
            rb[p] = *(const float4*)(blocks + (size_t)(kg + m) * NROW + col0 + sq * 4);
        }
    };

    // ---- split + STS one chunk from regs into buffer `buf` ----
    auto stsChunk = [&](int buf, const float4* ra, const float4* rb) {
        char* Ah = smem + OFF_AH + buf * CHUNK_B;
        char* Al = smem + OFF_AL + buf * CHUNK_B;
        char* Bh = smem + OFF_BH + buf * CHUNK_B;
        char* Bl = smem + OFF_BL + buf * CHUNK_B;
        #pragma unroll
        for (int p = 0; p < 2; ++p) {
            int m = sm0 + p * 32;
            uint32_t off = (uint32_t)(m * 128 + (((sq >> 1) ^ (m & 7)) * 16 + (sq & 1) * 8));
            uint32_t h01, l01, h23, l23;
            split2(ra[p].x, ra[p].y, h01, l01);
            split2(ra[p].z, ra[p].w, h23, l23);
            *(uint2*)(Ah + off) = make_uint2(h01, h23);
            *(uint2*)(Al + off) = make_uint2(l01, l23);
            split2(rb[p].x, rb[p].y, h01, l01);
            split2(rb[p].z, rb[p].w, h23, l23);
            *(uint2*)(Bh + off) = make_uint2(h01, h23);
            *(uint2*)(Bl + off) = make_uint2(l01, l23);
        }
    };

    // ---- compute setup: warp (wm, wn) -> 16x16 tile ----
    const int wm = wid & 3;
    const int wn = wid >> 2;
    const int m_base = wm * 16;
    const int n_base = wn * 16;

    const int a_row = m_base + (lid & 15);
    const int a_ch  = lid >> 4;
    const int a_rx  = a_row & 7;
    const uint32_t a_rowbase = (uint32_t)(a_row * 128);

    const int b_g   = (wn * 2 + (lid >> 4)) ^ (lid & 7);
    const uint32_t b_base = (uint32_t)((lid & 15) * 128 + b_g * 16);

    float acc[2][4] = {};

    auto computeChunk = [&](int buf) {
        const uint32_t aH = sbase + OFF_AH + buf * CHUNK_B;
        const uint32_t aL = sbase + OFF_AL + buf * CHUNK_B;
        const uint32_t bH = sbase + OFF_BH + buf * CHUNK_B;
        const uint32_t bL = sbase + OFF_BL + buf * CHUNK_B;
        uint32_t ah[4], al[4], bh[4], bl[4];
        #pragma unroll
        for (int ks = 0; ks < 4; ++ks) {
            uint32_t a_off = a_rowbase + (uint32_t)((((ks * 2 + a_ch) ^ a_rx)) * 16);
            uint32_t b_off = b_base + (uint32_t)(ks * 2048);
            ldsm_x4(ah, aH + a_off);
            ldsm_x4(al, aL + a_off);
            ldsm_x4_t(bh, bH + b_off);
            ldsm_x4_t(bl, bL + b_off);
            mma_bf16(acc[0], ah, bh[0], bh[1]);
            mma_bf16(acc[1], ah, bh[2], bh[3]);
            mma_bf16(acc[0], ah, bl[0], bl[1]);
            mma_bf16(acc[1], ah, bl[2], bl[3]);
            mma_bf16(acc[0], al, bh[0], bh[1]);
            mma_bf16(acc[1], al, bh[2], bh[3]);
        }
    };

    // ---- pipeline: prefetch distance 2, one sync per chunk ----
    float4 rA[2][2], rB[2][2];
    ldgChunk(0, rA[0], rB[0]);
    stsChunk(0, rA[0], rB[0]);
    ldgChunk(1, rA[1], rB[1]);
    __syncthreads();

    #pragma unroll
    for (int c = 0; c < 4; ++c) {
        if (c < 2) ldgChunk(c + 2, rA[c & 1], rB[c & 1]);
        if (c < 3) stsChunk((c + 1) & 1, rA[(c + 1) & 1], rB[(c + 1) & 1]);
        computeChunk(c & 1);
        if (c < 3) __syncthreads();
    }

    // ---- epilogue ----
    const int grp = lid >> 2;
    const int tc  = lid & 3;
    const int row0 = m_base + grp;
    const int row1 = row0 + 8;
    #pragma unroll
    for (int nh = 0; nh < 2; ++nh) {
        int col = col0 + n_base + nh * 8 + tc * 2;
        *(float2*)(out + (size_t)row0 * NROW + col) = make_float2(acc[nh][0], acc[nh][1]);
        *(float2*)(out + (size_t)row1 * NROW + col) = make_float2(acc[nh][2], acc[nh][3]);
    }
}

extern "C" void kernel_launch(void* const* d_in, const int* in_sizes, int n_in,
                              void* d_out, int out_size) {
    const float* x      = (const float*)d_in[0];
    const float* blocks = (const float*)d_in[1];
    float* out = (float*)d_out;

    cudaFuncSetAttribute(block_diag_hmma,
                         cudaFuncAttributeMaxDynamicSharedMemorySize, SMEM_BYTES);
    block_diag_hmma<<<128, 512, SMEM_BYTES>>>(x, blocks, out);
}